// round 9
// baseline (speedup 1.0000x reference)
#include <cuda_runtime.h>
#include <cuda_bf16.h>
#include <math.h>
#include <cstdint>
#include <cstddef>

// ----------------------------------------------------------------------------
// Problem constants
// ----------------------------------------------------------------------------
#define BB 16
#define SS 4096
#define DD 1024
#define KK 16
#define ITERS 3
#define SCALE 0.03125f            // D^-0.5 = 1/32
#define EPS_LN 1e-5f
#define EPS_ATTN 1e-8f

#define BK_ROWS ((size_t)BB * SS)         // 65536
#define SLOT_ELEMS ((size_t)BB * KK * DD) // 262144

// ----------------------------------------------------------------------------
// Scratch (device globals — no allocation allowed)
// ----------------------------------------------------------------------------
__device__ float g_kbuf[BK_ROWS * DD];        // 268 MB
__device__ float g_vbuf[BK_ROWS * DD];        // 268 MB
__device__ float g_attn[BK_ROWS * KK];        // [b][s][k]  4 MB
__device__ float g_partial[BB * 16 * KK];
__device__ float g_rowsum[BB * KK];
__device__ float g_slots[SLOT_ELEMS];
__device__ float g_lnbuf[SLOT_ELEMS];
__device__ float g_qbuf[SLOT_ELEMS];
__device__ float g_updbuf[SLOT_ELEMS];
__device__ float g_gibuf[(size_t)BB * KK * 3 * DD];
__device__ float g_ghbuf[(size_t)BB * KK * 3 * DD];
__device__ float g_h1buf[(size_t)BB * KK * 4 * DD];

// split-bf16 operands for the big K/V projection
__device__ __nv_bfloat16 g_tok_hi[BK_ROWS * DD];   // 128 MB
__device__ __nv_bfloat16 g_tok_lo[BK_ROWS * DD];   // 128 MB
__device__ __nv_bfloat16 g_wk_hi[DD * DD];
__device__ __nv_bfloat16 g_wk_lo[DD * DD];
__device__ __nv_bfloat16 g_wv_hi[DD * DD];
__device__ __nv_bfloat16 g_wv_lo[DD * DD];

// ----------------------------------------------------------------------------
// helpers
// ----------------------------------------------------------------------------
__device__ __forceinline__ unsigned f2tf(float x)
{
    unsigned u;
    asm("cvt.rna.tf32.f32 %0, %1;" : "=r"(u) : "f"(x));
    return u;
}

#define CP_ASYNC16(dst_u32, src_ptr) \
    asm volatile("cp.async.cg.shared.global [%0], [%1], 16;\n" :: "r"(dst_u32), "l"(src_ptr))
#define CP_COMMIT() asm volatile("cp.async.commit_group;\n")
#define CP_WAIT1()  asm volatile("cp.async.wait_group 1;\n")
#define CP_WAIT0()  asm volatile("cp.async.wait_group 0;\n")

#define LDSM4(r, addr) \
    asm volatile("ldmatrix.sync.aligned.m8n8.x4.shared.b16 {%0,%1,%2,%3}, [%4];" \
        : "=r"((r)[0]), "=r"((r)[1]), "=r"((r)[2]), "=r"((r)[3]) : "r"(addr))

#define MMA_BF16(d, a, b0v_, b1v_) \
    asm volatile("mma.sync.aligned.m16n8k16.row.col.f32.bf16.bf16.f32 " \
        "{%0,%1,%2,%3}, {%4,%5,%6,%7}, {%8,%9}, {%0,%1,%2,%3};\n" \
        : "+f"((d)[0]), "+f"((d)[1]), "+f"((d)[2]), "+f"((d)[3]) \
        : "r"((a)[0]), "r"((a)[1]), "r"((a)[2]), "r"((a)[3]), \
          "r"(b0v_), "r"(b1v_))

// ----------------------------------------------------------------------------
// split fp32 -> bf16 hi + bf16 lo (4 elems/thread)
// ----------------------------------------------------------------------------
__global__ void split_kernel(const float* __restrict__ src,
                             __nv_bfloat16* __restrict__ hi,
                             __nv_bfloat16* __restrict__ lo)
{
    size_t i = ((size_t)blockIdx.x * 256 + threadIdx.x) * 4;
    float4 x = *reinterpret_cast<const float4*>(src + i);
    __nv_bfloat16 h0 = __float2bfloat16(x.x);
    __nv_bfloat16 h1 = __float2bfloat16(x.y);
    __nv_bfloat16 h2 = __float2bfloat16(x.z);
    __nv_bfloat16 h3 = __float2bfloat16(x.w);
    __nv_bfloat16 l0 = __float2bfloat16(x.x - __bfloat162float(h0));
    __nv_bfloat16 l1 = __float2bfloat16(x.y - __bfloat162float(h1));
    __nv_bfloat16 l2 = __float2bfloat16(x.z - __bfloat162float(h2));
    __nv_bfloat16 l3 = __float2bfloat16(x.w - __bfloat162float(h3));
    __nv_bfloat162 hp0; hp0.x = h0; hp0.y = h1;
    __nv_bfloat162 hp1; hp1.x = h2; hp1.y = h3;
    __nv_bfloat162 lp0; lp0.x = l0; lp0.y = l1;
    __nv_bfloat162 lp1; lp1.x = l2; lp1.y = l3;
    *reinterpret_cast<__nv_bfloat162*>(hi + i)     = hp0;
    *reinterpret_cast<__nv_bfloat162*>(hi + i + 2) = hp1;
    *reinterpret_cast<__nv_bfloat162*>(lo + i)     = lp0;
    *reinterpret_cast<__nv_bfloat162*>(lo + i + 2) = lp1;
}

// ----------------------------------------------------------------------------
// Split-bf16 KV projection GEMM on the legacy tensor path (ldmatrix + mma.sync)
//   C[65536,1024] = A @ W^T + bias   via  hi*hi + hi*lo + lo*hi
// CTA 128x128, BK=32, double-buffered cp.async of pre-split bf16.
// 256 threads = 8 warps as 2 (M) x 4 (N): warp tile 64x32 -> MT=4, NT=4.
// Smem rows padded to 40 bf16 (80 B = 5x16B units -> ldmatrix conflict-free).
// grid (1024/128, 65536/128, 2)  z selects {K, V}.
// ----------------------------------------------------------------------------
#define KVB_ROWB 80                      // bytes per smem row
#define KVB_A_LO 10240                   // Alo offset within buffer
#define KVB_B_HI 20480                   // Bhi offset
#define KVB_B_LO 30720                   // Blo offset
#define KVB_BUF  40960                   // bytes per buffer
#define KVB_SMEM (2 * KVB_BUF)           // 81920

__global__ __launch_bounds__(256) void kv_gemm_bf16(
    const __nv_bfloat16* __restrict__ Ahi, const __nv_bfloat16* __restrict__ Alo,
    const __nv_bfloat16* __restrict__ WkHi, const __nv_bfloat16* __restrict__ WkLo,
    const __nv_bfloat16* __restrict__ WvHi, const __nv_bfloat16* __restrict__ WvLo,
    const float* __restrict__ bk, const float* __restrict__ bv,
    float* __restrict__ Ck, float* __restrict__ Cv)
{
    extern __shared__ __align__(16) char smem[];
    const bool isV = (blockIdx.z != 0);
    const __nv_bfloat16* Bh = isV ? WvHi : WkHi;
    const __nv_bfloat16* Bl = isV ? WvLo : WkLo;
    const float* bias = isV ? bv : bk;
    float* C = isV ? Cv : Ck;

    const int m0 = blockIdx.y * 128;
    const int n0 = blockIdx.x * 128;
    const int t = threadIdx.x;
    const int warp = t >> 5, lane = t & 31;
    const int wm = warp >> 2, wn = warp & 3;      // 2 x 4 warp grid
    const uint32_t sb = (uint32_t)__cvta_generic_to_shared(smem);

    float acc[4][4][4];
#pragma unroll
    for (int i = 0; i < 4; i++)
#pragma unroll
        for (int n = 0; n < 4; n++)
#pragma unroll
            for (int q = 0; q < 4; q++) acc[i][n][q] = 0.f;

    // stage chunk kt into buffer kt&1 (4x 16B cp.async per f-iter)
#define KVB_STAGE(kt_)                                                          \
    do {                                                                        \
        const uint32_t tb_ = sb + ((kt_) & 1) * KVB_BUF;                        \
        const int k0_ = (kt_) * 32;                                             \
        _Pragma("unroll")                                                       \
        for (int f = t; f < 512; f += 256) {                                    \
            int row = f >> 2, seg = f & 3;                                      \
            uint32_t dst = tb_ + row * KVB_ROWB + seg * 16;                     \
            size_t gA = (size_t)(m0 + row) * DD + k0_ + seg * 8;                \
            size_t gB = (size_t)(n0 + row) * DD + k0_ + seg * 8;                \
            CP_ASYNC16(dst,            Ahi + gA);                               \
            CP_ASYNC16(dst + KVB_A_LO, Alo + gA);                               \
            CP_ASYNC16(dst + KVB_B_HI, Bh + gB);                                \
            CP_ASYNC16(dst + KVB_B_LO, Bl + gB);                                \
        }                                                                       \
        CP_COMMIT();                                                            \
    } while (0)

    KVB_STAGE(0);

    const int lr = lane & 15;             // row within 16-row fragment pair
    const int kbh = (lane >> 4) * 16;     // +8 bf16 (=16 B) for k upper half

    for (int kt = 0; kt < 32; kt++) {
        if (kt + 1 < 32) { KVB_STAGE(kt + 1); CP_WAIT1(); }
        else             { CP_WAIT0(); }
        __syncthreads();

        const uint32_t tb = sb + (kt & 1) * KVB_BUF;
#pragma unroll
        for (int ks = 0; ks < 2; ks++) {
            const int kb = ks * 32 + kbh;            // byte offset into 32-elem row
            uint32_t ahi[4][4], alo[4][4], bhi[2][4], blo[2][4];
#pragma unroll
            for (int i = 0; i < 4; i++) {
                uint32_t ad = tb + (wm * 64 + i * 16 + lr) * KVB_ROWB + kb;
                LDSM4(ahi[i], ad);
                LDSM4(alo[i], ad + KVB_A_LO);
            }
#pragma unroll
            for (int j = 0; j < 2; j++) {
                uint32_t ad = tb + KVB_B_HI + (wn * 32 + j * 16 + lr) * KVB_ROWB + kb;
                LDSM4(bhi[j], ad);
                LDSM4(blo[j], ad + KVB_A_LO);   // Blo = Bhi + 10240
            }
#pragma unroll
            for (int i = 0; i < 4; i++)
#pragma unroll
                for (int n = 0; n < 4; n++) {
                    const int j = n >> 1, p = n & 1;
                    MMA_BF16(acc[i][n], ahi[i], bhi[j][p], bhi[j][p + 2]);
                    MMA_BF16(acc[i][n], ahi[i], blo[j][p], blo[j][p + 2]);
                    MMA_BF16(acc[i][n], alo[i], bhi[j][p], bhi[j][p + 2]);
                }
        }
        __syncthreads();
    }

    // epilogue: m16n8 accumulator layout
    const int r2 = lane >> 2, c2 = lane & 3;
#pragma unroll
    for (int i = 0; i < 4; i++) {
        const int row = m0 + wm * 64 + i * 16 + r2;
#pragma unroll
        for (int n = 0; n < 4; n++) {
            const int col = n0 + wn * 32 + n * 8 + 2 * c2;
            const float b0v = bias[col], b1v = bias[col + 1];
            float* p0 = &C[(size_t)row * DD + col];
            float* p1 = &C[(size_t)(row + 8) * DD + col];
            p0[0] = acc[i][n][0] + b0v; p0[1] = acc[i][n][1] + b1v;
            p1[0] = acc[i][n][2] + b0v; p1[1] = acc[i][n][3] + b1v;
        }
    }
#undef KVB_STAGE
}

// ----------------------------------------------------------------------------
// tf32 tensor-core NT GEMM (small per-iter GEMMs) — unchanged, passing
// ----------------------------------------------------------------------------
template <int BM, int BN, int WM, int WN, int ACT, bool ACCUM>
__global__ __launch_bounds__(256) void gemm_tf32(
    const float* __restrict__ A, const float* __restrict__ W,
    const float* __restrict__ bias, float* __restrict__ C,
    int N, int Kd)
{
    constexpr int BK = 16, PAD = 20;
    constexpr int MT = WM / 16, NT = WN / 8;
    constexpr int WARPS_N = BN / WN;

    __shared__ __align__(16) float As[2][BM][PAD];
    __shared__ __align__(16) float Bs[2][BN][PAD];

    const int t = threadIdx.x;
    const int warp = t >> 5, lane = t & 31;
    const int wm = warp / WARPS_N, wn = warp % WARPS_N;
    const int m0 = blockIdx.y * BM, n0 = blockIdx.x * BN;
    const int r = lane >> 2, c = lane & 3;

    float acc[MT][NT][4];
#pragma unroll
    for (int i = 0; i < MT; i++)
#pragma unroll
        for (int j = 0; j < NT; j++)
#pragma unroll
            for (int q = 0; q < 4; q++) acc[i][j][q] = 0.f;

    const int ntiles = Kd / BK;

    {
#pragma unroll
        for (int f = t; f < BM * 4; f += 256) {
            int row = f >> 2, cg = f & 3;
            unsigned dst = (unsigned)__cvta_generic_to_shared(&As[0][row][cg * 4]);
            CP_ASYNC16(dst, &A[(size_t)(m0 + row) * Kd + cg * 4]);
        }
#pragma unroll
        for (int f = t; f < BN * 4; f += 256) {
            int row = f >> 2, cg = f & 3;
            unsigned dst = (unsigned)__cvta_generic_to_shared(&Bs[0][row][cg * 4]);
            CP_ASYNC16(dst, &W[(size_t)(n0 + row) * Kd + cg * 4]);
        }
        CP_COMMIT();
    }

    for (int kt = 0; kt < ntiles; kt++) {
        if (kt + 1 < ntiles) {
            const int s = (kt + 1) & 1;
            const int k0 = (kt + 1) * BK;
#pragma unroll
            for (int f = t; f < BM * 4; f += 256) {
                int row = f >> 2, cg = f & 3;
                unsigned dst = (unsigned)__cvta_generic_to_shared(&As[s][row][cg * 4]);
                CP_ASYNC16(dst, &A[(size_t)(m0 + row) * Kd + k0 + cg * 4]);
            }
#pragma unroll
            for (int f = t; f < BN * 4; f += 256) {
                int row = f >> 2, cg = f & 3;
                unsigned dst = (unsigned)__cvta_generic_to_shared(&Bs[s][row][cg * 4]);
                CP_ASYNC16(dst, &W[(size_t)(n0 + row) * Kd + k0 + cg * 4]);
            }
            CP_COMMIT();
            CP_WAIT1();
        } else {
            CP_WAIT0();
        }
        __syncthreads();

        const int buf = kt & 1;
#pragma unroll
        for (int ks = 0; ks < BK; ks += 8) {
            unsigned af[MT][4], bf[NT][2];
#pragma unroll
            for (int i = 0; i < MT; i++) {
                const int mr = wm * WM + i * 16 + r;
                af[i][0] = f2tf(As[buf][mr][ks + c]);
                af[i][1] = f2tf(As[buf][mr + 8][ks + c]);
                af[i][2] = f2tf(As[buf][mr][ks + c + 4]);
                af[i][3] = f2tf(As[buf][mr + 8][ks + c + 4]);
            }
#pragma unroll
            for (int j = 0; j < NT; j++) {
                const int nr = wn * WN + j * 8 + r;
                bf[j][0] = f2tf(Bs[buf][nr][ks + c]);
                bf[j][1] = f2tf(Bs[buf][nr][ks + c + 4]);
            }
#pragma unroll
            for (int i = 0; i < MT; i++)
#pragma unroll
                for (int j = 0; j < NT; j++) {
                    asm volatile(
                        "mma.sync.aligned.m16n8k8.row.col.f32.tf32.tf32.f32 "
                        "{%0,%1,%2,%3}, {%4,%5,%6,%7}, {%8,%9}, {%0,%1,%2,%3};\n"
                        : "+f"(acc[i][j][0]), "+f"(acc[i][j][1]),
                          "+f"(acc[i][j][2]), "+f"(acc[i][j][3])
                        : "r"(af[i][0]), "r"(af[i][1]), "r"(af[i][2]), "r"(af[i][3]),
                          "r"(bf[j][0]), "r"(bf[j][1]));
                }
        }
        __syncthreads();
    }

#pragma unroll
    for (int i = 0; i < MT; i++) {
        const int row = m0 + wm * WM + i * 16 + r;
#pragma unroll
        for (int j = 0; j < NT; j++) {
            const int col = n0 + wn * WN + j * 8 + 2 * c;
            const float b0v = bias[col], b1v = bias[col + 1];
            float v0 = acc[i][j][0] + b0v;
            float v1 = acc[i][j][1] + b1v;
            float v2 = acc[i][j][2] + b0v;
            float v3 = acc[i][j][3] + b1v;
            float* p0 = &C[(size_t)row * N + col];
            float* p1 = &C[(size_t)(row + 8) * N + col];
            if (ACCUM) {
                v0 += p0[0]; v1 += p0[1];
                v2 += p1[0]; v3 += p1[1];
            }
            if (ACT == 1) {
                v0 = 0.5f * v0 * (1.f + erff(v0 * 0.70710678118654752f));
                v1 = 0.5f * v1 * (1.f + erff(v1 * 0.70710678118654752f));
                v2 = 0.5f * v2 * (1.f + erff(v2 * 0.70710678118654752f));
                v3 = 0.5f * v3 * (1.f + erff(v3 * 0.70710678118654752f));
            }
            p0[0] = v0; p0[1] = v1;
            p1[0] = v2; p1[1] = v3;
        }
    }
}

// ----------------------------------------------------------------------------
// slots init
// ----------------------------------------------------------------------------
__global__ void init_slots_kernel(const float* __restrict__ mu, float* __restrict__ slots)
{
    int idx = blockIdx.x * 256 + threadIdx.x;
    slots[idx] = mu[idx & 16383];
}

// ----------------------------------------------------------------------------
// LayerNorm
// ----------------------------------------------------------------------------
__global__ void ln_rows_kernel(const float* __restrict__ x, const float* __restrict__ g,
                               const float* __restrict__ b, float* __restrict__ y)
{
    int row = blockIdx.x;
    int t = threadIdx.x;
    const float4* xr = reinterpret_cast<const float4*>(x + (size_t)row * DD);
    float4 v = xr[t];
    float s1 = v.x + v.y + v.z + v.w;
    float s2 = v.x * v.x + v.y * v.y + v.z * v.z + v.w * v.w;
    int lane = t & 31, w = t >> 5;
#pragma unroll
    for (int off = 16; off > 0; off >>= 1) {
        s1 += __shfl_down_sync(0xffffffffu, s1, off);
        s2 += __shfl_down_sync(0xffffffffu, s2, off);
    }
    __shared__ float ss1[8], ss2[8];
    __shared__ float smu, srstd;
    if (lane == 0) { ss1[w] = s1; ss2[w] = s2; }
    __syncthreads();
    if (t == 0) {
        float S = 0.f, Q = 0.f;
#pragma unroll
        for (int i = 0; i < 8; i++) { S += ss1[i]; Q += ss2[i]; }
        float mu = S * (1.f / DD);
        float var = Q * (1.f / DD) - mu * mu;
        smu = mu; srstd = rsqrtf(var + EPS_LN);
    }
    __syncthreads();
    float mu = smu, rr = srstd;
    float4 gv = reinterpret_cast<const float4*>(g)[t];
    float4 bv = reinterpret_cast<const float4*>(b)[t];
    float4 o;
    o.x = (v.x - mu) * rr * gv.x + bv.x;
    o.y = (v.y - mu) * rr * gv.y + bv.y;
    o.z = (v.z - mu) * rr * gv.z + bv.z;
    o.w = (v.w - mu) * rr * gv.w + bv.w;
    reinterpret_cast<float4*>(y + (size_t)row * DD)[t] = o;
}

// ----------------------------------------------------------------------------
// logits
// ----------------------------------------------------------------------------
__global__ __launch_bounds__(256) void logits_kernel(
    const float* __restrict__ q, const float* __restrict__ kbuf,
    float* __restrict__ attn)
{
    int b = blockIdx.y;
    int s0 = blockIdx.x * 128;
    __shared__ __align__(16) float sK[128][36];
    __shared__ __align__(16) float sQ[16][36];
    int t = threadIdx.x;
    int kidx = t & 15;
    int sg   = (t >> 4) * 8;
    const float* kb = kbuf + ((size_t)b * SS + s0) * DD;
    const float* qb = q + (size_t)b * KK * DD;
    float acc[8];
#pragma unroll
    for (int i = 0; i < 8; i++) acc[i] = 0.f;

    for (int d0 = 0; d0 < DD; d0 += 32) {
#pragma unroll
        for (int f = t; f < 1024; f += 256) {
            int row = f >> 3, cg = f & 7;
            float4 v = *reinterpret_cast<const float4*>(&kb[(size_t)row * DD + d0 + cg * 4]);
            sK[row][cg * 4 + 0] = v.x; sK[row][cg * 4 + 1] = v.y;
            sK[row][cg * 4 + 2] = v.z; sK[row][cg * 4 + 3] = v.w;
        }
        if (t < 128) {
            int row = t >> 3, cg = t & 7;
            float4 v = *reinterpret_cast<const float4*>(&qb[(size_t)row * DD + d0 + cg * 4]);
            sQ[row][cg * 4 + 0] = v.x; sQ[row][cg * 4 + 1] = v.y;
            sQ[row][cg * 4 + 2] = v.z; sQ[row][cg * 4 + 3] = v.w;
        }
        __syncthreads();
#pragma unroll
        for (int d = 0; d < 32; d += 4) {
            float4 qv = *reinterpret_cast<const float4*>(&sQ[kidx][d]);
#pragma unroll
            for (int i = 0; i < 8; i++) {
                float4 kv = *reinterpret_cast<const float4*>(&sK[sg + i][d]);
                acc[i] += kv.x * qv.x + kv.y * qv.y + kv.z * qv.z + kv.w * qv.w;
            }
        }
        __syncthreads();
    }
#pragma unroll
    for (int i = 0; i < 8; i++)
        attn[((size_t)b * SS + s0 + sg + i) * KK + kidx] = acc[i] * SCALE;
}

// ----------------------------------------------------------------------------
// softmax over k + partial row sums
// ----------------------------------------------------------------------------
__global__ void softmax_kernel(float* __restrict__ attn, float* __restrict__ partial)
{
    int blk = blockIdx.x;
    int b = blk >> 4;
    int s = (blk & 15) * 256 + threadIdx.x;
    float* a = attn + ((size_t)b * SS + s) * KK;
    float v[16];
    float4* a4 = reinterpret_cast<float4*>(a);
#pragma unroll
    for (int i = 0; i < 4; i++) {
        float4 x = a4[i];
        v[i * 4 + 0] = x.x; v[i * 4 + 1] = x.y; v[i * 4 + 2] = x.z; v[i * 4 + 3] = x.w;
    }
    float mx = v[0];
#pragma unroll
    for (int k = 1; k < 16; k++) mx = fmaxf(mx, v[k]);
    float sum = 0.f;
#pragma unroll
    for (int k = 0; k < 16; k++) { v[k] = expf(v[k] - mx); sum += v[k]; }
    float inv = 1.f / sum;
#pragma unroll
    for (int k = 0; k < 16; k++) v[k] *= inv;
#pragma unroll
    for (int i = 0; i < 4; i++) {
        float4 x;
        x.x = v[i * 4 + 0]; x.y = v[i * 4 + 1]; x.z = v[i * 4 + 2]; x.w = v[i * 4 + 3];
        a4[i] = x;
    }
    int lane = threadIdx.x & 31, w = threadIdx.x >> 5;
    __shared__ float ws[8][16];
#pragma unroll
    for (int k = 0; k < 16; k++) {
        float x = v[k];
#pragma unroll
        for (int off = 16; off > 0; off >>= 1) x += __shfl_down_sync(0xffffffffu, x, off);
        if (lane == 0) ws[w][k] = x;
    }
    __syncthreads();
    if (threadIdx.x < 16) {
        float sacc = 0.f;
#pragma unroll
        for (int ww = 0; ww < 8; ww++) sacc += ws[ww][threadIdx.x];
        partial[(size_t)blk * KK + threadIdx.x] = sacc;
    }
}

__global__ void rowsum_kernel(const float* __restrict__ partial, float* __restrict__ rowsum)
{
    int t = threadIdx.x;
    int b = t >> 4, k = t & 15;
    float s = 0.f;
#pragma unroll
    for (int c = 0; c < 16; c++) s += partial[((size_t)(b * 16 + c)) * KK + k];
    rowsum[t] = s;
}

// ----------------------------------------------------------------------------
// updates = attn_n @ v
// ----------------------------------------------------------------------------
__global__ __launch_bounds__(256) void updates_kernel(
    const float* __restrict__ attn, const float* __restrict__ rowsum,
    const float* __restrict__ vbuf, float* __restrict__ upd)
{
    int b = blockIdx.y;
    int d0 = blockIdx.x * 128;
    __shared__ float sV[32][128];
    __shared__ __align__(16) float sA[32][20];
    __shared__ float rs[16];
    int t = threadIdx.x;
    if (t < 16) rs[t] = 1.f / (rowsum[b * 16 + t] + EPS_ATTN);
    int dl = t & 127;
    int kg = (t >> 7) * 8;
    float acc[8];
#pragma unroll
    for (int j = 0; j < 8; j++) acc[j] = 0.f;
    const float* vb = vbuf + (size_t)b * SS * DD;
    const float* ab = attn + (size_t)b * SS * KK;
    __syncthreads();

    for (int s0 = 0; s0 < SS; s0 += 32) {
#pragma unroll
        for (int f = t; f < 1024; f += 256) {
            int row = f >> 5, cg = f & 31;
            float4 v = *reinterpret_cast<const float4*>(&vb[(size_t)(s0 + row) * DD + d0 + cg * 4]);
            sV[row][cg * 4 + 0] = v.x; sV[row][cg * 4 + 1] = v.y;
            sV[row][cg * 4 + 2] = v.z; sV[row][cg * 4 + 3] = v.w;
        }
#pragma unroll
        for (int f = t; f < 512; f += 256) {
            int srow = f >> 4, k = f & 15;
            sA[srow][k] = ab[(size_t)(s0 + srow) * KK + k];
        }
        __syncthreads();
#pragma unroll 8
        for (int s = 0; s < 32; s++) {
            float va = sV[s][dl];
            float4 a0 = *reinterpret_cast<const float4*>(&sA[s][kg]);
            float4 a1 = *reinterpret_cast<const float4*>(&sA[s][kg + 4]);
            acc[0] += a0.x * va; acc[1] += a0.y * va; acc[2] += a0.z * va; acc[3] += a0.w * va;
            acc[4] += a1.x * va; acc[5] += a1.y * va; acc[6] += a1.z * va; acc[7] += a1.w * va;
        }
        __syncthreads();
    }
#pragma unroll
    for (int j = 0; j < 8; j++)
        upd[((size_t)b * KK + kg + j) * DD + d0 + dl] = acc[j] * rs[kg + j];
}

// ----------------------------------------------------------------------------
// GRU combine
// ----------------------------------------------------------------------------
__global__ void gru_kernel(const float* __restrict__ gi, const float* __restrict__ gh,
                           float* __restrict__ slots)
{
    int idx = blockIdx.x * 256 + threadIdx.x;
    int m = idx >> 10, d = idx & 1023;
    size_t base = (size_t)m * 3072 + d;
    float ir = gi[base], iz = gi[base + 1024], in_ = gi[base + 2048];
    float hr = gh[base], hz = gh[base + 1024], hn  = gh[base + 2048];
    float r = 1.f / (1.f + expf(-(ir + hr)));
    float z = 1.f / (1.f + expf(-(iz + hz)));
    float n = tanhf(in_ + r * hn);
    float sp = slots[idx];
    slots[idx] = (1.f - z) * n + z * sp;
}

// ----------------------------------------------------------------------------
// output writers
// ----------------------------------------------------------------------------
__global__ void copy_kernel(const float* __restrict__ src, float* __restrict__ dst)
{
    int idx = blockIdx.x * 256 + threadIdx.x;
    dst[idx] = src[idx];
}

__global__ void attn_out_kernel(const float* __restrict__ attn, float* __restrict__ out)
{
    int idx = blockIdx.x * 256 + threadIdx.x;
    int s = idx & 4095;
    int k = (idx >> 12) & 15;
    int b = idx >> 16;
    out[idx] = attn[((size_t)b * SS + s) * KK + k];
}

// ----------------------------------------------------------------------------
// host
// ----------------------------------------------------------------------------
extern "C" void kernel_launch(void* const* d_in, const int* in_sizes, int n_in,
                              void* d_out, int out_size)
{
    const float* tokens  = (const float*)d_in[0];
    const float* slot_mu = (const float*)d_in[1];
    const float* Wq   = (const float*)d_in[2];
    const float* bq   = (const float*)d_in[3];
    const float* Wk   = (const float*)d_in[4];
    const float* bk   = (const float*)d_in[5];
    const float* Wv   = (const float*)d_in[6];
    const float* bv   = (const float*)d_in[7];
    const float* W_ih = (const float*)d_in[8];
    const float* b_ih = (const float*)d_in[9];
    const float* W_hh = (const float*)d_in[10];
    const float* b_hh = (const float*)d_in[11];
    const float* W1   = (const float*)d_in[12];
    const float* b1   = (const float*)d_in[13];
    const float* W2   = (const float*)d_in[14];
    const float* b2   = (const float*)d_in[15];
    const float* gam_slots = (const float*)d_in[16];
    const float* bet_slots = (const float*)d_in[17];
    const float* gam_mlp   = (const float*)d_in[18];
    const float* bet_mlp   = (const float*)d_in[19];
    float* out = (float*)d_out;

    float *kbuf, *vbuf, *attn, *partial, *rowsum, *slots, *lnbuf, *qbuf, *updbuf, *gibuf, *ghbuf, *h1buf;
    __nv_bfloat16 *tok_hi, *tok_lo, *wk_hi, *wk_lo, *wv_hi, *wv_lo;
    cudaGetSymbolAddress((void**)&kbuf,   g_kbuf);
    cudaGetSymbolAddress((void**)&vbuf,   g_vbuf);
    cudaGetSymbolAddress((void**)&attn,   g_attn);
    cudaGetSymbolAddress((void**)&partial,g_partial);
    cudaGetSymbolAddress((void**)&rowsum, g_rowsum);
    cudaGetSymbolAddress((void**)&slots,  g_slots);
    cudaGetSymbolAddress((void**)&lnbuf,  g_lnbuf);
    cudaGetSymbolAddress((void**)&qbuf,   g_qbuf);
    cudaGetSymbolAddress((void**)&updbuf, g_updbuf);
    cudaGetSymbolAddress((void**)&gibuf,  g_gibuf);
    cudaGetSymbolAddress((void**)&ghbuf,  g_ghbuf);
    cudaGetSymbolAddress((void**)&h1buf,  g_h1buf);
    cudaGetSymbolAddress((void**)&tok_hi, g_tok_hi);
    cudaGetSymbolAddress((void**)&tok_lo, g_tok_lo);
    cudaGetSymbolAddress((void**)&wk_hi,  g_wk_hi);
    cudaGetSymbolAddress((void**)&wk_lo,  g_wk_lo);
    cudaGetSymbolAddress((void**)&wv_hi,  g_wv_hi);
    cudaGetSymbolAddress((void**)&wv_lo,  g_wv_lo);

    cudaFuncSetAttribute(kv_gemm_bf16, cudaFuncAttributeMaxDynamicSharedMemorySize, KVB_SMEM);

    // split fp32 -> bf16 hi/lo
    split_kernel<<<(unsigned)(BK_ROWS * DD / 1024), 256>>>(tokens, tok_hi, tok_lo);
    split_kernel<<<DD * DD / 1024, 256>>>(Wk, wk_hi, wk_lo);
    split_kernel<<<DD * DD / 1024, 256>>>(Wv, wv_hi, wv_lo);

    // K/V projections: split-bf16 ldmatrix + mma.sync (z: 0=K, 1=V)
    kv_gemm_bf16<<<dim3(DD / 128, (unsigned)(BK_ROWS / 128), 2), 256, KVB_SMEM>>>(
        tok_hi, tok_lo, wk_hi, wk_lo, wv_hi, wv_lo, bk, bv, kbuf, vbuf);

    init_slots_kernel<<<SLOT_ELEMS / 256, 256>>>(slot_mu, slots);

    for (int it = 0; it < ITERS; it++) {
        ln_rows_kernel<<<BB * KK, 256>>>(slots, gam_slots, bet_slots, lnbuf);
        gemm_tf32<64, 64, 32, 16, 0, false><<<dim3(DD / 64, BB * KK / 64), 256>>>(lnbuf, Wq, bq, qbuf, DD, DD);

        logits_kernel<<<dim3(SS / 128, BB), 256>>>(qbuf, kbuf, attn);
        softmax_kernel<<<BB * 16, 256>>>(attn, partial);
        rowsum_kernel<<<1, 256>>>(partial, rowsum);

        updates_kernel<<<dim3(DD / 128, BB), 256>>>(attn, rowsum, vbuf, updbuf);

        gemm_tf32<64, 64, 32, 16, 0, false><<<dim3(3 * DD / 64, BB * KK / 64), 256>>>(updbuf, W_ih, b_ih, gibuf, 3 * DD, DD);
        gemm_tf32<64, 64, 32, 16, 0, false><<<dim3(3 * DD / 64, BB * KK / 64), 256>>>(slots, W_hh, b_hh, ghbuf, 3 * DD, DD);
        gru_kernel<<<SLOT_ELEMS / 256, 256>>>(gibuf, ghbuf, slots);

        ln_rows_kernel<<<BB * KK, 256>>>(slots, gam_mlp, bet_mlp, lnbuf);
        gemm_tf32<64, 64, 32, 16, 1, false><<<dim3(4 * DD / 64, BB * KK / 64), 256>>>(lnbuf, W1, b1, h1buf, 4 * DD, DD);
        gemm_tf32<64, 64, 32, 16, 0, true><<<dim3(DD / 64, BB * KK / 64), 256>>>(h1buf, W2, b2, slots, DD, 4 * DD);
    }

    copy_kernel<<<SLOT_ELEMS / 256, 256>>>(slots, out);
    attn_out_kernel<<<(BB * KK * SS) / 256, 256>>>(attn, out + SLOT_ELEMS);
}

// round 14
// speedup vs baseline: 1.9991x; 1.9991x over previous
#include <cuda_runtime.h>
#include <cuda_bf16.h>
#include <math.h>
#include <cstdint>
#include <cstddef>

// ----------------------------------------------------------------------------
// Problem constants
// ----------------------------------------------------------------------------
#define BB 16
#define SS 4096
#define DD 1024
#define KK 16
#define ITERS 3
#define SCALE 0.03125f            // D^-0.5 = 1/32
#define EPS_LN 1e-5f
#define EPS_ATTN 1e-8f

#define BK_ROWS ((size_t)BB * SS)         // 65536
#define SLOT_ELEMS ((size_t)BB * KK * DD) // 262144

// ----------------------------------------------------------------------------
// Scratch (device globals — zero-init, no allocation allowed)
// ----------------------------------------------------------------------------
__device__ float g_attn[BK_ROWS * KK];        // [b][s][16]  4 MB
__device__ float g_partial[BB * 16 * KK];
__device__ float g_rowsum[BB * KK];
__device__ float g_rowf[BB * KK];             // rowsum/(rowsum+eps)
__device__ float g_qd[BB * KK];               // q . bk
__device__ float g_slots[SLOT_ELEMS];
__device__ float g_lnbuf[SLOT_ELEMS];
__device__ float g_qbuf[SLOT_ELEMS];
__device__ float g_qkbuf[SLOT_ELEMS];         // q' = q @ Wk
__device__ float g_updbuf[SLOT_ELEMS];        // U = attn_n @ tokens
__device__ float g_upd2[SLOT_ELEMS];          // U @ Wv^T + f*bv
__device__ float g_gibuf[(size_t)BB * KK * 3 * DD];
__device__ float g_ghbuf[(size_t)BB * KK * 3 * DD];
__device__ float g_h1buf[(size_t)BB * KK * 4 * DD];
__device__ float g_wkT[DD * DD];              // Wk transposed
__device__ float g_zero[4 * DD];              // zero bias (device globals zero-init)

// ----------------------------------------------------------------------------
// helpers
// ----------------------------------------------------------------------------
__device__ __forceinline__ unsigned f2tf(float x)
{
    unsigned u;
    asm("cvt.rna.tf32.f32 %0, %1;" : "=r"(u) : "f"(x));
    return u;
}

__device__ __forceinline__ void tf32split(float x, unsigned& h, unsigned& l)
{
    h = f2tf(x);
    l = f2tf(x - __uint_as_float(h));
}

#define CP_ASYNC16(dst_u32, src_ptr) \
    asm volatile("cp.async.cg.shared.global [%0], [%1], 16;\n" :: "r"(dst_u32), "l"(src_ptr))
#define CP_COMMIT() asm volatile("cp.async.commit_group;\n")
#define CP_WAIT1()  asm volatile("cp.async.wait_group 1;\n")
#define CP_WAIT0()  asm volatile("cp.async.wait_group 0;\n")

#define MMA_TF32(d, a0,a1,a2,a3, b0v_,b1v_) \
    asm volatile("mma.sync.aligned.m16n8k8.row.col.f32.tf32.tf32.f32 " \
        "{%0,%1,%2,%3}, {%4,%5,%6,%7}, {%8,%9}, {%0,%1,%2,%3};\n" \
        : "+f"((d)[0]), "+f"((d)[1]), "+f"((d)[2]), "+f"((d)[3]) \
        : "r"(a0), "r"(a1), "r"(a2), "r"(a3), "r"(b0v_), "r"(b1v_))

// ----------------------------------------------------------------------------
// tf32 tensor-core NT GEMM.  C[M,N] = A[M,Kd] @ W[N,Kd]^T + bias
// PREC=1: single tf32 product (~5e-4).  PREC=3: hi/lo split, 3 products (~fp32).
// RB: bias scaled by per-row factor rowf[m].
// ----------------------------------------------------------------------------
template <int BM, int BN, int WM, int WN, int ACT, bool ACCUM, int PREC, bool RB>
__global__ __launch_bounds__(256) void gemm_tf32(
    const float* __restrict__ A, const float* __restrict__ W,
    const float* __restrict__ bias, const float* __restrict__ rowf,
    float* __restrict__ C, int N, int Kd)
{
    constexpr int BK = 16, PAD = 20;
    constexpr int MT = WM / 16, NT = WN / 8;
    constexpr int WARPS_N = BN / WN;

    __shared__ __align__(16) float As[2][BM][PAD];
    __shared__ __align__(16) float Bs[2][BN][PAD];

    const int t = threadIdx.x;
    const int warp = t >> 5, lane = t & 31;
    const int wm = warp / WARPS_N, wn = warp % WARPS_N;
    const int m0 = blockIdx.y * BM, n0 = blockIdx.x * BN;
    const int r = lane >> 2, c = lane & 3;

    float acc[MT][NT][4];
#pragma unroll
    for (int i = 0; i < MT; i++)
#pragma unroll
        for (int j = 0; j < NT; j++)
#pragma unroll
            for (int q = 0; q < 4; q++) acc[i][j][q] = 0.f;

    const int ntiles = Kd / BK;

    {
#pragma unroll
        for (int f = t; f < BM * 4; f += 256) {
            int row = f >> 2, cg = f & 3;
            unsigned dst = (unsigned)__cvta_generic_to_shared(&As[0][row][cg * 4]);
            CP_ASYNC16(dst, &A[(size_t)(m0 + row) * Kd + cg * 4]);
        }
#pragma unroll
        for (int f = t; f < BN * 4; f += 256) {
            int row = f >> 2, cg = f & 3;
            unsigned dst = (unsigned)__cvta_generic_to_shared(&Bs[0][row][cg * 4]);
            CP_ASYNC16(dst, &W[(size_t)(n0 + row) * Kd + cg * 4]);
        }
        CP_COMMIT();
    }

    for (int kt = 0; kt < ntiles; kt++) {
        if (kt + 1 < ntiles) {
            const int s = (kt + 1) & 1;
            const int k0 = (kt + 1) * BK;
#pragma unroll
            for (int f = t; f < BM * 4; f += 256) {
                int row = f >> 2, cg = f & 3;
                unsigned dst = (unsigned)__cvta_generic_to_shared(&As[s][row][cg * 4]);
                CP_ASYNC16(dst, &A[(size_t)(m0 + row) * Kd + k0 + cg * 4]);
            }
#pragma unroll
            for (int f = t; f < BN * 4; f += 256) {
                int row = f >> 2, cg = f & 3;
                unsigned dst = (unsigned)__cvta_generic_to_shared(&Bs[s][row][cg * 4]);
                CP_ASYNC16(dst, &W[(size_t)(n0 + row) * Kd + k0 + cg * 4]);
            }
            CP_COMMIT();
            CP_WAIT1();
        } else {
            CP_WAIT0();
        }
        __syncthreads();

        const int buf = kt & 1;
#pragma unroll
        for (int ks = 0; ks < BK; ks += 8) {
            unsigned afh[MT][4], bfh[NT][2];
            unsigned afl[MT][4], bfl[NT][2];
#pragma unroll
            for (int i = 0; i < MT; i++) {
                const int mr = wm * WM + i * 16 + r;
                float x0 = As[buf][mr][ks + c];
                float x1 = As[buf][mr + 8][ks + c];
                float x2 = As[buf][mr][ks + c + 4];
                float x3 = As[buf][mr + 8][ks + c + 4];
                if (PREC == 3) {
                    tf32split(x0, afh[i][0], afl[i][0]);
                    tf32split(x1, afh[i][1], afl[i][1]);
                    tf32split(x2, afh[i][2], afl[i][2]);
                    tf32split(x3, afh[i][3], afl[i][3]);
                } else {
                    afh[i][0] = f2tf(x0); afh[i][1] = f2tf(x1);
                    afh[i][2] = f2tf(x2); afh[i][3] = f2tf(x3);
                }
            }
#pragma unroll
            for (int j = 0; j < NT; j++) {
                const int nr = wn * WN + j * 8 + r;
                float y0 = Bs[buf][nr][ks + c];
                float y1 = Bs[buf][nr][ks + c + 4];
                if (PREC == 3) {
                    tf32split(y0, bfh[j][0], bfl[j][0]);
                    tf32split(y1, bfh[j][1], bfl[j][1]);
                } else {
                    bfh[j][0] = f2tf(y0); bfh[j][1] = f2tf(y1);
                }
            }
#pragma unroll
            for (int i = 0; i < MT; i++)
#pragma unroll
                for (int j = 0; j < NT; j++) {
                    MMA_TF32(acc[i][j], afh[i][0], afh[i][1], afh[i][2], afh[i][3],
                             bfh[j][0], bfh[j][1]);
                    if (PREC == 3) {
                        MMA_TF32(acc[i][j], afh[i][0], afh[i][1], afh[i][2], afh[i][3],
                                 bfl[j][0], bfl[j][1]);
                        MMA_TF32(acc[i][j], afl[i][0], afl[i][1], afl[i][2], afl[i][3],
                                 bfh[j][0], bfh[j][1]);
                    }
                }
        }
        __syncthreads();
    }

#pragma unroll
    for (int i = 0; i < MT; i++) {
        const int row = m0 + wm * WM + i * 16 + r;
        const float f0 = RB ? rowf[row] : 1.f;
        const float f1 = RB ? rowf[row + 8] : 1.f;
#pragma unroll
        for (int j = 0; j < NT; j++) {
            const int col = n0 + wn * WN + j * 8 + 2 * c;
            const float b0v = bias[col], b1v = bias[col + 1];
            float v0 = acc[i][j][0] + f0 * b0v;
            float v1 = acc[i][j][1] + f0 * b1v;
            float v2 = acc[i][j][2] + f1 * b0v;
            float v3 = acc[i][j][3] + f1 * b1v;
            float* p0 = &C[(size_t)row * N + col];
            float* p1 = &C[(size_t)(row + 8) * N + col];
            if (ACCUM) {
                v0 += p0[0]; v1 += p0[1];
                v2 += p1[0]; v3 += p1[1];
            }
            if (ACT == 1) {
                v0 = 0.5f * v0 * (1.f + erff(v0 * 0.70710678118654752f));
                v1 = 0.5f * v1 * (1.f + erff(v1 * 0.70710678118654752f));
                v2 = 0.5f * v2 * (1.f + erff(v2 * 0.70710678118654752f));
                v3 = 0.5f * v3 * (1.f + erff(v3 * 0.70710678118654752f));
            }
            p0[0] = v0; p0[1] = v1;
            p1[0] = v2; p1[1] = v3;
        }
    }
}

// ----------------------------------------------------------------------------
// transpose 1024x1024: dst[e][d] = src[d][e]
// ----------------------------------------------------------------------------
__global__ void transpose_kernel(const float* __restrict__ src, float* __restrict__ dst)
{
    __shared__ float tile[32][33];
    int x = blockIdx.x * 32 + threadIdx.x;
    int y0 = blockIdx.y * 32 + threadIdx.y;
#pragma unroll
    for (int j = 0; j < 32; j += 8)
        tile[threadIdx.y + j][threadIdx.x] = src[(size_t)(y0 + j) * DD + x];
    __syncthreads();
    x = blockIdx.y * 32 + threadIdx.x;
    y0 = blockIdx.x * 32 + threadIdx.y;
#pragma unroll
    for (int j = 0; j < 32; j += 8)
        dst[(size_t)(y0 + j) * DD + x] = tile[threadIdx.x][threadIdx.y + j];
}

// ----------------------------------------------------------------------------
// qd[m] = dot(q[m,:], bk)  — 256 rows, 1 warp/row
// ----------------------------------------------------------------------------
__global__ void qdot_kernel(const float* __restrict__ q, const float* __restrict__ bk,
                            float* __restrict__ qd)
{
    int gw = (blockIdx.x * 256 + threadIdx.x) >> 5;   // 0..255
    int lane = threadIdx.x & 31;
    const float* row = q + (size_t)gw * DD;
    float s = 0.f;
#pragma unroll
    for (int d = lane * 4; d < DD; d += 128) {
        float4 v = *reinterpret_cast<const float4*>(row + d);
        float4 b = *reinterpret_cast<const float4*>(bk + d);
        s += v.x * b.x + v.y * b.y + v.z * b.z + v.w * b.w;
    }
#pragma unroll
    for (int off = 16; off > 0; off >>= 1) s += __shfl_down_sync(0xffffffffu, s, off);
    if (lane == 0) qd[gw] = s;
}

// ----------------------------------------------------------------------------
// slots init
// ----------------------------------------------------------------------------
__global__ void init_slots_kernel(const float* __restrict__ mu, float* __restrict__ slots)
{
    int idx = blockIdx.x * 256 + threadIdx.x;
    slots[idx] = mu[idx & 16383];
}

// ----------------------------------------------------------------------------
// LayerNorm
// ----------------------------------------------------------------------------
__global__ void ln_rows_kernel(const float* __restrict__ x, const float* __restrict__ g,
                               const float* __restrict__ b, float* __restrict__ y)
{
    int row = blockIdx.x;
    int t = threadIdx.x;
    const float4* xr = reinterpret_cast<const float4*>(x + (size_t)row * DD);
    float4 v = xr[t];
    float s1 = v.x + v.y + v.z + v.w;
    float s2 = v.x * v.x + v.y * v.y + v.z * v.z + v.w * v.w;
    int lane = t & 31, w = t >> 5;
#pragma unroll
    for (int off = 16; off > 0; off >>= 1) {
        s1 += __shfl_down_sync(0xffffffffu, s1, off);
        s2 += __shfl_down_sync(0xffffffffu, s2, off);
    }
    __shared__ float ss1[8], ss2[8];
    __shared__ float smu, srstd;
    if (lane == 0) { ss1[w] = s1; ss2[w] = s2; }
    __syncthreads();
    if (t == 0) {
        float S = 0.f, Q = 0.f;
#pragma unroll
        for (int i = 0; i < 8; i++) { S += ss1[i]; Q += ss2[i]; }
        float mu = S * (1.f / DD);
        float var = Q * (1.f / DD) - mu * mu;
        smu = mu; srstd = rsqrtf(var + EPS_LN);
    }
    __syncthreads();
    float mu = smu, rr = srstd;
    float4 gv = reinterpret_cast<const float4*>(g)[t];
    float4 bv = reinterpret_cast<const float4*>(b)[t];
    float4 o;
    o.x = (v.x - mu) * rr * gv.x + bv.x;
    o.y = (v.y - mu) * rr * gv.y + bv.y;
    o.z = (v.z - mu) * rr * gv.z + bv.z;
    o.w = (v.w - mu) * rr * gv.w + bv.w;
    reinterpret_cast<float4*>(y + (size_t)row * DD)[t] = o;
}

// ----------------------------------------------------------------------------
// logits[b][s][k] = SCALE * (q'[b][k] . tokens[b][s] + qd[b][k])
// ----------------------------------------------------------------------------
__global__ __launch_bounds__(256) void logits_kernel(
    const float* __restrict__ qk, const float* __restrict__ tokens,
    const float* __restrict__ qd, float* __restrict__ attn)
{
    int b = blockIdx.y;
    int s0 = blockIdx.x * 128;
    __shared__ __align__(16) float sK[128][36];
    __shared__ __align__(16) float sQ[16][36];
    int t = threadIdx.x;
    int kidx = t & 15;
    int sg   = (t >> 4) * 8;
    const float* kb = tokens + ((size_t)b * SS + s0) * DD;
    const float* qb = qk + (size_t)b * KK * DD;
    float acc[8];
#pragma unroll
    for (int i = 0; i < 8; i++) acc[i] = 0.f;

    for (int d0 = 0; d0 < DD; d0 += 32) {
#pragma unroll
        for (int f = t; f < 1024; f += 256) {
            int row = f >> 3, cg = f & 7;
            float4 v = *reinterpret_cast<const float4*>(&kb[(size_t)row * DD + d0 + cg * 4]);
            sK[row][cg * 4 + 0] = v.x; sK[row][cg * 4 + 1] = v.y;
            sK[row][cg * 4 + 2] = v.z; sK[row][cg * 4 + 3] = v.w;
        }
        if (t < 128) {
            int row = t >> 3, cg = t & 7;
            float4 v = *reinterpret_cast<const float4*>(&qb[(size_t)row * DD + d0 + cg * 4]);
            sQ[row][cg * 4 + 0] = v.x; sQ[row][cg * 4 + 1] = v.y;
            sQ[row][cg * 4 + 2] = v.z; sQ[row][cg * 4 + 3] = v.w;
        }
        __syncthreads();
#pragma unroll
        for (int d = 0; d < 32; d += 4) {
            float4 qv = *reinterpret_cast<const float4*>(&sQ[kidx][d]);
#pragma unroll
            for (int i = 0; i < 8; i++) {
                float4 kv = *reinterpret_cast<const float4*>(&sK[sg + i][d]);
                acc[i] += kv.x * qv.x + kv.y * qv.y + kv.z * qv.z + kv.w * qv.w;
            }
        }
        __syncthreads();
    }
    const float qbias = qd[b * KK + kidx];
#pragma unroll
    for (int i = 0; i < 8; i++)
        attn[((size_t)b * SS + s0 + sg + i) * KK + kidx] = (acc[i] + qbias) * SCALE;
}

// ----------------------------------------------------------------------------
// softmax over k + partial row sums
// ----------------------------------------------------------------------------
__global__ void softmax_kernel(float* __restrict__ attn, float* __restrict__ partial)
{
    int blk = blockIdx.x;
    int b = blk >> 4;
    int s = (blk & 15) * 256 + threadIdx.x;
    float* a = attn + ((size_t)b * SS + s) * KK;
    float v[16];
    float4* a4 = reinterpret_cast<float4*>(a);
#pragma unroll
    for (int i = 0; i < 4; i++) {
        float4 x = a4[i];
        v[i * 4 + 0] = x.x; v[i * 4 + 1] = x.y; v[i * 4 + 2] = x.z; v[i * 4 + 3] = x.w;
    }
    float mx = v[0];
#pragma unroll
    for (int k = 1; k < 16; k++) mx = fmaxf(mx, v[k]);
    float sum = 0.f;
#pragma unroll
    for (int k = 0; k < 16; k++) { v[k] = expf(v[k] - mx); sum += v[k]; }
    float inv = 1.f / sum;
#pragma unroll
    for (int k = 0; k < 16; k++) v[k] *= inv;
#pragma unroll
    for (int i = 0; i < 4; i++) {
        float4 x;
        x.x = v[i * 4 + 0]; x.y = v[i * 4 + 1]; x.z = v[i * 4 + 2]; x.w = v[i * 4 + 3];
        a4[i] = x;
    }
    int lane = threadIdx.x & 31, w = threadIdx.x >> 5;
    __shared__ float ws[8][16];
#pragma unroll
    for (int k = 0; k < 16; k++) {
        float x = v[k];
#pragma unroll
        for (int off = 16; off > 0; off >>= 1) x += __shfl_down_sync(0xffffffffu, x, off);
        if (lane == 0) ws[w][k] = x;
    }
    __syncthreads();
    if (threadIdx.x < 16) {
        float sacc = 0.f;
#pragma unroll
        for (int ww = 0; ww < 8; ww++) sacc += ws[ww][threadIdx.x];
        partial[(size_t)blk * KK + threadIdx.x] = sacc;
    }
}

__global__ void rowsum_kernel(const float* __restrict__ partial, float* __restrict__ rowsum,
                              float* __restrict__ rowf)
{
    int t = threadIdx.x;
    int b = t >> 4, k = t & 15;
    float s = 0.f;
#pragma unroll
    for (int c = 0; c < 16; c++) s += partial[((size_t)(b * 16 + c)) * KK + k];
    rowsum[t] = s;
    rowf[t] = s / (s + EPS_ATTN);
}

// ----------------------------------------------------------------------------
// U[b][k][d] = (1/(rowsum+eps)) * sum_s attn[b][s][k] * tokens[b][s][d]
// ----------------------------------------------------------------------------
__global__ __launch_bounds__(256) void updates_kernel(
    const float* __restrict__ attn, const float* __restrict__ rowsum,
    const float* __restrict__ tokens, float* __restrict__ upd)
{
    int b = blockIdx.y;
    int d0 = blockIdx.x * 128;
    __shared__ float sV[32][128];
    __shared__ __align__(16) float sA[32][20];
    __shared__ float rs[16];
    int t = threadIdx.x;
    if (t < 16) rs[t] = 1.f / (rowsum[b * 16 + t] + EPS_ATTN);
    int dl = t & 127;
    int kg = (t >> 7) * 8;
    float acc[8];
#pragma unroll
    for (int j = 0; j < 8; j++) acc[j] = 0.f;
    const float* vb = tokens + (size_t)b * SS * DD;
    const float* ab = attn + (size_t)b * SS * KK;
    __syncthreads();

    for (int s0 = 0; s0 < SS; s0 += 32) {
#pragma unroll
        for (int f = t; f < 1024; f += 256) {
            int row = f >> 5, cg = f & 31;
            float4 v = *reinterpret_cast<const float4*>(&vb[(size_t)(s0 + row) * DD + d0 + cg * 4]);
            sV[row][cg * 4 + 0] = v.x; sV[row][cg * 4 + 1] = v.y;
            sV[row][cg * 4 + 2] = v.z; sV[row][cg * 4 + 3] = v.w;
        }
#pragma unroll
        for (int f = t; f < 512; f += 256) {
            int srow = f >> 4, k = f & 15;
            sA[srow][k] = ab[(size_t)(s0 + srow) * KK + k];
        }
        __syncthreads();
#pragma unroll 8
        for (int s = 0; s < 32; s++) {
            float va = sV[s][dl];
            float4 a0 = *reinterpret_cast<const float4*>(&sA[s][kg]);
            float4 a1 = *reinterpret_cast<const float4*>(&sA[s][kg + 4]);
            acc[0] += a0.x * va; acc[1] += a0.y * va; acc[2] += a0.z * va; acc[3] += a0.w * va;
            acc[4] += a1.x * va; acc[5] += a1.y * va; acc[6] += a1.z * va; acc[7] += a1.w * va;
        }
        __syncthreads();
    }
#pragma unroll
    for (int j = 0; j < 8; j++)
        upd[((size_t)b * KK + kg + j) * DD + d0 + dl] = acc[j] * rs[kg + j];
}

// ----------------------------------------------------------------------------
// GRU combine
// ----------------------------------------------------------------------------
__global__ void gru_kernel(const float* __restrict__ gi, const float* __restrict__ gh,
                           float* __restrict__ slots)
{
    int idx = blockIdx.x * 256 + threadIdx.x;
    int m = idx >> 10, d = idx & 1023;
    size_t base = (size_t)m * 3072 + d;
    float ir = gi[base], iz = gi[base + 1024], in_ = gi[base + 2048];
    float hr = gh[base], hz = gh[base + 1024], hn  = gh[base + 2048];
    float r = 1.f / (1.f + expf(-(ir + hr)));
    float z = 1.f / (1.f + expf(-(iz + hz)));
    float n = tanhf(in_ + r * hn);
    float sp = slots[idx];
    slots[idx] = (1.f - z) * n + z * sp;
}

// ----------------------------------------------------------------------------
// output writers
// ----------------------------------------------------------------------------
__global__ void copy_kernel(const float* __restrict__ src, float* __restrict__ dst)
{
    int idx = blockIdx.x * 256 + threadIdx.x;
    dst[idx] = src[idx];
}

__global__ void attn_out_kernel(const float* __restrict__ attn, float* __restrict__ out)
{
    int idx = blockIdx.x * 256 + threadIdx.x;
    int s = idx & 4095;
    int k = (idx >> 12) & 15;
    int b = idx >> 16;
    out[idx] = attn[((size_t)b * SS + s) * KK + k];
}

// ----------------------------------------------------------------------------
// host
// ----------------------------------------------------------------------------
extern "C" void kernel_launch(void* const* d_in, const int* in_sizes, int n_in,
                              void* d_out, int out_size)
{
    const float* tokens  = (const float*)d_in[0];
    const float* slot_mu = (const float*)d_in[1];
    const float* Wq   = (const float*)d_in[2];
    const float* bq   = (const float*)d_in[3];
    const float* Wk   = (const float*)d_in[4];
    const float* bk   = (const float*)d_in[5];
    const float* Wv   = (const float*)d_in[6];
    const float* bv   = (const float*)d_in[7];
    const float* W_ih = (const float*)d_in[8];
    const float* b_ih = (const float*)d_in[9];
    const float* W_hh = (const float*)d_in[10];
    const float* b_hh = (const float*)d_in[11];
    const float* W1   = (const float*)d_in[12];
    const float* b1   = (const float*)d_in[13];
    const float* W2   = (const float*)d_in[14];
    const float* b2   = (const float*)d_in[15];
    const float* gam_slots = (const float*)d_in[16];
    const float* bet_slots = (const float*)d_in[17];
    const float* gam_mlp   = (const float*)d_in[18];
    const float* bet_mlp   = (const float*)d_in[19];
    float* out = (float*)d_out;

    float *attn, *partial, *rowsum, *rowf, *qd, *slots, *lnbuf, *qbuf, *qkbuf,
          *updbuf, *upd2, *gibuf, *ghbuf, *h1buf, *wkT, *zero;
    cudaGetSymbolAddress((void**)&attn,   g_attn);
    cudaGetSymbolAddress((void**)&partial,g_partial);
    cudaGetSymbolAddress((void**)&rowsum, g_rowsum);
    cudaGetSymbolAddress((void**)&rowf,   g_rowf);
    cudaGetSymbolAddress((void**)&qd,     g_qd);
    cudaGetSymbolAddress((void**)&slots,  g_slots);
    cudaGetSymbolAddress((void**)&lnbuf,  g_lnbuf);
    cudaGetSymbolAddress((void**)&qbuf,   g_qbuf);
    cudaGetSymbolAddress((void**)&qkbuf,  g_qkbuf);
    cudaGetSymbolAddress((void**)&updbuf, g_updbuf);
    cudaGetSymbolAddress((void**)&upd2,   g_upd2);
    cudaGetSymbolAddress((void**)&gibuf,  g_gibuf);
    cudaGetSymbolAddress((void**)&ghbuf,  g_ghbuf);
    cudaGetSymbolAddress((void**)&h1buf,  g_h1buf);
    cudaGetSymbolAddress((void**)&wkT,    g_wkT);
    cudaGetSymbolAddress((void**)&zero,   g_zero);

    // one-time prep
    transpose_kernel<<<dim3(32, 32), dim3(32, 8)>>>(Wk, wkT);
    init_slots_kernel<<<SLOT_ELEMS / 256, 256>>>(slot_mu, slots);

    for (int it = 0; it < ITERS; it++) {
        // q = LN(slots) @ Wq^T + bq          (high precision)
        ln_rows_kernel<<<BB * KK, 256>>>(slots, gam_slots, bet_slots, lnbuf);
        gemm_tf32<64, 64, 32, 16, 0, false, 3, false>
            <<<dim3(DD / 64, BB * KK / 64), 256>>>(lnbuf, Wq, bq, nullptr, qbuf, DD, DD);

        // q' = q @ Wk  (via Wk^T),  qd = q . bk
        gemm_tf32<64, 64, 32, 16, 0, false, 3, false>
            <<<dim3(DD / 64, BB * KK / 64), 256>>>(qbuf, wkT, zero, nullptr, qkbuf, DD, DD);
        qdot_kernel<<<32, 256>>>(qbuf, bk, qd);

        // logits on raw tokens -> softmax over slots -> row sums
        logits_kernel<<<dim3(SS / 128, BB), 256>>>(qkbuf, tokens, qd, attn);
        softmax_kernel<<<BB * 16, 256>>>(attn, partial);
        rowsum_kernel<<<1, 256>>>(partial, rowsum, rowf);

        // U = attn_n @ tokens, then updates = U @ Wv^T + f*bv
        updates_kernel<<<dim3(DD / 128, BB), 256>>>(attn, rowsum, tokens, updbuf);
        gemm_tf32<64, 64, 32, 16, 0, false, 3, true>
            <<<dim3(DD / 64, BB * KK / 64), 256>>>(updbuf, Wv, bv, rowf, upd2, DD, DD);

        // GRU
        gemm_tf32<64, 64, 32, 16, 0, false, 1, false>
            <<<dim3(3 * DD / 64, BB * KK / 64), 256>>>(upd2, W_ih, b_ih, nullptr, gibuf, 3 * DD, DD);
        gemm_tf32<64, 64, 32, 16, 0, false, 1, false>
            <<<dim3(3 * DD / 64, BB * KK / 64), 256>>>(slots, W_hh, b_hh, nullptr, ghbuf, 3 * DD, DD);
        gru_kernel<<<SLOT_ELEMS / 256, 256>>>(gibuf, ghbuf, slots);

        // MLP residual
        ln_rows_kernel<<<BB * KK, 256>>>(slots, gam_mlp, bet_mlp, lnbuf);
        gemm_tf32<64, 64, 32, 16, 1, false, 1, false>
            <<<dim3(4 * DD / 64, BB * KK / 64), 256>>>(lnbuf, W1, b1, nullptr, h1buf, 4 * DD, DD);
        gemm_tf32<64, 64, 32, 16, 0, true, 1, false>
            <<<dim3(DD / 64, BB * KK / 64), 256>>>(h1buf, W2, b2, nullptr, slots, DD, 4 * DD);
    }

    copy_kernel<<<SLOT_ELEMS / 256, 256>>>(slots, out);
    attn_out_kernel<<<(BB * KK * SS) / 256, 256>>>(attn, out + SLOT_ELEMS);
}

// round 17
// speedup vs baseline: 3.1135x; 1.5575x over previous
#include <cuda_runtime.h>
#include <cuda_bf16.h>
#include <math.h>
#include <cstdint>
#include <cstddef>

// ----------------------------------------------------------------------------
// Problem constants
// ----------------------------------------------------------------------------
#define BB 16
#define SS 4096
#define DD 1024
#define KK 16
#define ITERS 3
#define SCALE 0.03125f            // D^-0.5 = 1/32
#define EPS_LN 1e-5f
#define EPS_ATTN 1e-8f

#define BK_ROWS ((size_t)BB * SS)         // 65536
#define SLOT_ELEMS ((size_t)BB * KK * DD) // 262144

// ----------------------------------------------------------------------------
// Scratch (device globals — zero-init, no allocation allowed)
// ----------------------------------------------------------------------------
__device__ float g_attn[BK_ROWS * KK];        // [b][s][16]  4 MB
__device__ float g_partial[BB * 16 * KK];
__device__ float g_rowsum[BB * KK];
__device__ float g_rowf[BB * KK];             // rowsum/(rowsum+eps)
__device__ float g_qd[BB * KK];               // q . bk
__device__ float g_slots[SLOT_ELEMS];
__device__ float g_lnbuf[SLOT_ELEMS];
__device__ float g_qkbuf[SLOT_ELEMS];         // q' = LN @ P + c
__device__ float g_updbuf[SLOT_ELEMS];        // U = attn_n @ tokens
__device__ float g_upd2[SLOT_ELEMS];          // U @ Wv^T + f*bv
__device__ float g_gibuf[(size_t)BB * KK * 3 * DD];
__device__ float g_ghbuf[(size_t)BB * KK * 3 * DD];
__device__ float g_h1buf[(size_t)BB * KK * 4 * DD];
__device__ float g_wkT[DD * DD];              // Wk transposed
__device__ float g_wqT[DD * DD];              // Wq transposed
__device__ float g_Pt[DD * DD];               // Pt[e,f] = sum_d Wk[d,e] Wq[d,f]
__device__ float g_wqbk[DD];                  // sum_d Wq[d,f] bk[d]
__device__ float g_cvec[DD];                  // sum_d bq[d] Wk[d,e]
__device__ float g_bqbk[32];                  // bq . bk (elem 0)
__device__ float g_zero[4 * DD];              // zero bias

// ----------------------------------------------------------------------------
// helpers
// ----------------------------------------------------------------------------
__device__ __forceinline__ unsigned f2tf(float x)
{
    unsigned u;
    asm("cvt.rna.tf32.f32 %0, %1;" : "=r"(u) : "f"(x));
    return u;
}

__device__ __forceinline__ void tf32split(float x, unsigned& h, unsigned& l)
{
    h = f2tf(x);
    l = f2tf(x - __uint_as_float(h));
}

#define CP_ASYNC16(dst_u32, src_ptr) \
    asm volatile("cp.async.cg.shared.global [%0], [%1], 16;\n" :: "r"(dst_u32), "l"(src_ptr))
#define CP_COMMIT() asm volatile("cp.async.commit_group;\n")
#define CP_WAIT1()  asm volatile("cp.async.wait_group 1;\n")
#define CP_WAIT0()  asm volatile("cp.async.wait_group 0;\n")

#define MMA_TF32(d, a0,a1,a2,a3, b0v_,b1v_) \
    asm volatile("mma.sync.aligned.m16n8k8.row.col.f32.tf32.tf32.f32 " \
        "{%0,%1,%2,%3}, {%4,%5,%6,%7}, {%8,%9}, {%0,%1,%2,%3};\n" \
        : "+f"((d)[0]), "+f"((d)[1]), "+f"((d)[2]), "+f"((d)[3]) \
        : "r"(a0), "r"(a1), "r"(a2), "r"(a3), "r"(b0v_), "r"(b1v_))

// ----------------------------------------------------------------------------
// tf32 tensor-core NT GEMM.  C[M,N] = A[M,Kd] @ W[N,Kd]^T + bias
// PREC=1: single tf32 product.  PREC=3: hi/lo split, 3 products (~fp32).
// RB: bias scaled by per-row factor rowf[m].
// ----------------------------------------------------------------------------
template <int BM, int BN, int WM, int WN, int ACT, bool ACCUM, int PREC, bool RB>
__global__ __launch_bounds__(256) void gemm_tf32(
    const float* __restrict__ A, const float* __restrict__ W,
    const float* __restrict__ bias, const float* __restrict__ rowf,
    float* __restrict__ C, int N, int Kd)
{
    constexpr int BK = 16, PAD = 20;
    constexpr int MT = WM / 16, NT = WN / 8;
    constexpr int WARPS_N = BN / WN;

    __shared__ __align__(16) float As[2][BM][PAD];
    __shared__ __align__(16) float Bs[2][BN][PAD];

    const int t = threadIdx.x;
    const int warp = t >> 5, lane = t & 31;
    const int wm = warp / WARPS_N, wn = warp % WARPS_N;
    const int m0 = blockIdx.y * BM, n0 = blockIdx.x * BN;
    const int r = lane >> 2, c = lane & 3;

    float acc[MT][NT][4];
#pragma unroll
    for (int i = 0; i < MT; i++)
#pragma unroll
        for (int j = 0; j < NT; j++)
#pragma unroll
            for (int q = 0; q < 4; q++) acc[i][j][q] = 0.f;

    const int ntiles = Kd / BK;

    {
#pragma unroll
        for (int f = t; f < BM * 4; f += 256) {
            int row = f >> 2, cg = f & 3;
            unsigned dst = (unsigned)__cvta_generic_to_shared(&As[0][row][cg * 4]);
            CP_ASYNC16(dst, &A[(size_t)(m0 + row) * Kd + cg * 4]);
        }
#pragma unroll
        for (int f = t; f < BN * 4; f += 256) {
            int row = f >> 2, cg = f & 3;
            unsigned dst = (unsigned)__cvta_generic_to_shared(&Bs[0][row][cg * 4]);
            CP_ASYNC16(dst, &W[(size_t)(n0 + row) * Kd + cg * 4]);
        }
        CP_COMMIT();
    }

    for (int kt = 0; kt < ntiles; kt++) {
        if (kt + 1 < ntiles) {
            const int s = (kt + 1) & 1;
            const int k0 = (kt + 1) * BK;
#pragma unroll
            for (int f = t; f < BM * 4; f += 256) {
                int row = f >> 2, cg = f & 3;
                unsigned dst = (unsigned)__cvta_generic_to_shared(&As[s][row][cg * 4]);
                CP_ASYNC16(dst, &A[(size_t)(m0 + row) * Kd + k0 + cg * 4]);
            }
#pragma unroll
            for (int f = t; f < BN * 4; f += 256) {
                int row = f >> 2, cg = f & 3;
                unsigned dst = (unsigned)__cvta_generic_to_shared(&Bs[s][row][cg * 4]);
                CP_ASYNC16(dst, &W[(size_t)(n0 + row) * Kd + k0 + cg * 4]);
            }
            CP_COMMIT();
            CP_WAIT1();
        } else {
            CP_WAIT0();
        }
        __syncthreads();

        const int buf = kt & 1;
#pragma unroll
        for (int ks = 0; ks < BK; ks += 8) {
            unsigned afh[MT][4], bfh[NT][2];
            unsigned afl[MT][4], bfl[NT][2];
#pragma unroll
            for (int i = 0; i < MT; i++) {
                const int mr = wm * WM + i * 16 + r;
                float x0 = As[buf][mr][ks + c];
                float x1 = As[buf][mr + 8][ks + c];
                float x2 = As[buf][mr][ks + c + 4];
                float x3 = As[buf][mr + 8][ks + c + 4];
                if (PREC == 3) {
                    tf32split(x0, afh[i][0], afl[i][0]);
                    tf32split(x1, afh[i][1], afl[i][1]);
                    tf32split(x2, afh[i][2], afl[i][2]);
                    tf32split(x3, afh[i][3], afl[i][3]);
                } else {
                    afh[i][0] = f2tf(x0); afh[i][1] = f2tf(x1);
                    afh[i][2] = f2tf(x2); afh[i][3] = f2tf(x3);
                }
            }
#pragma unroll
            for (int j = 0; j < NT; j++) {
                const int nr = wn * WN + j * 8 + r;
                float y0 = Bs[buf][nr][ks + c];
                float y1 = Bs[buf][nr][ks + c + 4];
                if (PREC == 3) {
                    tf32split(y0, bfh[j][0], bfl[j][0]);
                    tf32split(y1, bfh[j][1], bfl[j][1]);
                } else {
                    bfh[j][0] = f2tf(y0); bfh[j][1] = f2tf(y1);
                }
            }
#pragma unroll
            for (int i = 0; i < MT; i++)
#pragma unroll
                for (int j = 0; j < NT; j++) {
                    MMA_TF32(acc[i][j], afh[i][0], afh[i][1], afh[i][2], afh[i][3],
                             bfh[j][0], bfh[j][1]);
                    if (PREC == 3) {
                        MMA_TF32(acc[i][j], afh[i][0], afh[i][1], afh[i][2], afh[i][3],
                                 bfl[j][0], bfl[j][1]);
                        MMA_TF32(acc[i][j], afl[i][0], afl[i][1], afl[i][2], afl[i][3],
                                 bfh[j][0], bfh[j][1]);
                    }
                }
        }
        __syncthreads();
    }

#pragma unroll
    for (int i = 0; i < MT; i++) {
        const int row = m0 + wm * WM + i * 16 + r;
        const float f0 = RB ? rowf[row] : 1.f;
        const float f1 = RB ? rowf[row + 8] : 1.f;
#pragma unroll
        for (int j = 0; j < NT; j++) {
            const int col = n0 + wn * WN + j * 8 + 2 * c;
            const float b0v = bias[col], b1v = bias[col + 1];
            float v0 = acc[i][j][0] + f0 * b0v;
            float v1 = acc[i][j][1] + f0 * b1v;
            float v2 = acc[i][j][2] + f1 * b0v;
            float v3 = acc[i][j][3] + f1 * b1v;
            float* p0 = &C[(size_t)row * N + col];
            float* p1 = &C[(size_t)(row + 8) * N + col];
            if (ACCUM) {
                v0 += p0[0]; v1 += p0[1];
                v2 += p1[0]; v3 += p1[1];
            }
            if (ACT == 1) {
                v0 = 0.5f * v0 * (1.f + erff(v0 * 0.70710678118654752f));
                v1 = 0.5f * v1 * (1.f + erff(v1 * 0.70710678118654752f));
                v2 = 0.5f * v2 * (1.f + erff(v2 * 0.70710678118654752f));
                v3 = 0.5f * v3 * (1.f + erff(v3 * 0.70710678118654752f));
            }
            p0[0] = v0; p0[1] = v1;
            p1[0] = v2; p1[1] = v3;
        }
    }
}

// ----------------------------------------------------------------------------
// logits on tensor cores (split-tf32, ~fp32 exact):
//   attn[b][s][k] = SCALE * (sum_d q'[b][k][d] * tokens[b][s][d] + qd[b][k])
// M=16 (k), N=256 s per block, inner d=1024.  grid (SS/256, BB), 256 thr.
// ----------------------------------------------------------------------------
#define LTC_SMEM ((2 * 16 * 36 + 2 * 256 * 36) * 4)   // 78336 B

__global__ __launch_bounds__(256) void logits_tc(
    const float* __restrict__ qk, const float* __restrict__ tokens,
    const float* __restrict__ qd, float* __restrict__ attn)
{
    extern __shared__ __align__(16) float dsm[];
    float* sQ = dsm;                  // [2][16][36]
    float* sT = dsm + 2 * 16 * 36;    // [2][256][36]
    const int b = blockIdx.y;
    const int s0 = blockIdx.x * 256;
    const int t = threadIdx.x;
    const int w = t >> 5, lane = t & 31;
    const int r = lane >> 2, c = lane & 3;

    const float* tok = tokens + ((size_t)b * SS + s0) * DD;
    const float* qb  = qk + (size_t)b * KK * DD;
    const uint32_t sQb = (uint32_t)__cvta_generic_to_shared(sQ);
    const uint32_t sTb = (uint32_t)__cvta_generic_to_shared(sT);

    float acc[4][4];
#pragma unroll
    for (int j = 0; j < 4; j++)
#pragma unroll
        for (int q = 0; q < 4; q++) acc[j][q] = 0.f;

#define LTC_STAGE(kt_)                                                             \
    do {                                                                           \
        const int buf_ = (kt_) & 1;                                                \
        const int d0_ = (kt_) * 32;                                                \
        if (t < 128) {                                                             \
            int row = t >> 3, cg = t & 7;                                          \
            CP_ASYNC16(sQb + (buf_ * 16 + row) * 144 + cg * 16,                    \
                       qb + (size_t)row * DD + d0_ + cg * 4);                      \
        }                                                                          \
        _Pragma("unroll")                                                          \
        for (int i = 0; i < 8; i++) {                                              \
            int f = t + i * 256;                                                   \
            int row = f >> 3, cg = f & 7;                                          \
            CP_ASYNC16(sTb + (buf_ * 256 + row) * 144 + cg * 16,                   \
                       tok + (size_t)row * DD + d0_ + cg * 4);                     \
        }                                                                          \
        CP_COMMIT();                                                               \
    } while (0)

    LTC_STAGE(0);

    for (int kt = 0; kt < 32; kt++) {
        if (kt + 1 < 32) { LTC_STAGE(kt + 1); CP_WAIT1(); }
        else             { CP_WAIT0(); }
        __syncthreads();
        const float* q_ = sQ + (kt & 1) * 16 * 36;
        const float* t_ = sT + (kt & 1) * 256 * 36;
#pragma unroll
        for (int ks = 0; ks < 4; ks++) {
            const int kb = ks * 8;
            unsigned ah[4], al[4];
            tf32split(q_[r * 36 + kb + c],           ah[0], al[0]);
            tf32split(q_[(r + 8) * 36 + kb + c],     ah[1], al[1]);
            tf32split(q_[r * 36 + kb + c + 4],       ah[2], al[2]);
            tf32split(q_[(r + 8) * 36 + kb + c + 4], ah[3], al[3]);
#pragma unroll
            for (int j = 0; j < 4; j++) {
                const int n = w * 32 + j * 8 + r;
                unsigned bh0, bl0, bh1, bl1;
                tf32split(t_[n * 36 + kb + c],     bh0, bl0);
                tf32split(t_[n * 36 + kb + c + 4], bh1, bl1);
                MMA_TF32(acc[j], ah[0], ah[1], ah[2], ah[3], bh0, bh1);
                MMA_TF32(acc[j], ah[0], ah[1], ah[2], ah[3], bl0, bl1);
                MMA_TF32(acc[j], al[0], al[1], al[2], al[3], bh0, bh1);
            }
        }
        __syncthreads();
    }

    const float qd0 = qd[b * KK + r];
    const float qd1 = qd[b * KK + r + 8];
#pragma unroll
    for (int j = 0; j < 4; j++) {
        const int s = s0 + w * 32 + j * 8 + 2 * c;
        float* ap = attn + ((size_t)b * SS + s) * KK;
        ap[r]          = (acc[j][0] + qd0) * SCALE;
        ap[KK + r]     = (acc[j][1] + qd0) * SCALE;
        ap[r + 8]      = (acc[j][2] + qd1) * SCALE;
        ap[KK + r + 8] = (acc[j][3] + qd1) * SCALE;
    }
#undef LTC_STAGE
}

// ----------------------------------------------------------------------------
// updates on tensor cores (split-tf32):
//   U[b][k][d] = rs[k] * sum_s attn[b][s][k] * tokens[b][s][d]
// M=16 (k), N=128 d per block, inner s=4096.  grid (DD/128, BB), 256 thr.
// ----------------------------------------------------------------------------
__global__ __launch_bounds__(256) void updates_tc(
    const float* __restrict__ attn, const float* __restrict__ rowsum,
    const float* __restrict__ tokens, float* __restrict__ upd)
{
    __shared__ __align__(16) float sA[2][32][24];
    __shared__ __align__(16) float sT[2][32][136];
    const int b = blockIdx.y;
    const int d0 = blockIdx.x * 128;
    const int t = threadIdx.x;
    const int w = t >> 5, lane = t & 31;
    const int r = lane >> 2, c = lane & 3;

    const float* tok = tokens + (size_t)b * SS * DD;
    const float* ab  = attn + (size_t)b * SS * KK;
    const uint32_t sAb = (uint32_t)__cvta_generic_to_shared(sA);
    const uint32_t sTb = (uint32_t)__cvta_generic_to_shared(sT);

    float acc[2][4];
#pragma unroll
    for (int j = 0; j < 2; j++)
#pragma unroll
        for (int q = 0; q < 4; q++) acc[j][q] = 0.f;

#define UTC_STAGE(ct_)                                                             \
    do {                                                                           \
        const int buf_ = (ct_) & 1;                                                \
        const int sc0_ = (ct_) * 32;                                               \
        if (t < 128) {                                                             \
            int row = t >> 2, cg = t & 3;                                          \
            CP_ASYNC16(sAb + (buf_ * 32 + row) * 96 + cg * 16,                     \
                       ab + (size_t)(sc0_ + row) * KK + cg * 4);                   \
        }                                                                          \
        _Pragma("unroll")                                                          \
        for (int i = 0; i < 4; i++) {                                              \
            int f = t + i * 256;                                                   \
            int row = f >> 5, cg = f & 31;                                         \
            CP_ASYNC16(sTb + (buf_ * 32 + row) * 544 + cg * 16,                    \
                       tok + (size_t)(sc0_ + row) * DD + d0 + cg * 4);             \
        }                                                                          \
        CP_COMMIT();                                                               \
    } while (0)

    UTC_STAGE(0);

    for (int ct = 0; ct < 128; ct++) {
        if (ct + 1 < 128) { UTC_STAGE(ct + 1); CP_WAIT1(); }
        else              { CP_WAIT0(); }
        __syncthreads();
        const float (*A_)[24]  = sA[ct & 1];
        const float (*T_)[136] = sT[ct & 1];
#pragma unroll
        for (int ks = 0; ks < 4; ks++) {
            const int kb = ks * 8;
            unsigned ah[4], al[4];
            tf32split(A_[kb + c][r],          ah[0], al[0]);
            tf32split(A_[kb + c][r + 8],      ah[1], al[1]);
            tf32split(A_[kb + c + 4][r],      ah[2], al[2]);
            tf32split(A_[kb + c + 4][r + 8],  ah[3], al[3]);
#pragma unroll
            for (int j = 0; j < 2; j++) {
                const int dl = w * 16 + j * 8 + r;
                unsigned bh0, bl0, bh1, bl1;
                tf32split(T_[kb + c][dl],     bh0, bl0);
                tf32split(T_[kb + c + 4][dl], bh1, bl1);
                MMA_TF32(acc[j], ah[0], ah[1], ah[2], ah[3], bh0, bh1);
                MMA_TF32(acc[j], ah[0], ah[1], ah[2], ah[3], bl0, bl1);
                MMA_TF32(acc[j], al[0], al[1], al[2], al[3], bh0, bh1);
            }
        }
        __syncthreads();
    }

    const float rs0 = 1.f / (rowsum[b * KK + r] + EPS_ATTN);
    const float rs1 = 1.f / (rowsum[b * KK + r + 8] + EPS_ATTN);
#pragma unroll
    for (int j = 0; j < 2; j++) {
        const int dl = d0 + w * 16 + j * 8 + 2 * c;
        float* p0 = upd + ((size_t)b * KK + r) * DD + dl;
        float* p1 = upd + ((size_t)b * KK + r + 8) * DD + dl;
        p0[0] = acc[j][0] * rs0; p0[1] = acc[j][1] * rs0;
        p1[0] = acc[j][2] * rs1; p1[1] = acc[j][3] * rs1;
    }
#undef UTC_STAGE
}

// ----------------------------------------------------------------------------
// transpose 1024x1024: dst[e][d] = src[d][e]
// ----------------------------------------------------------------------------
__global__ void transpose_kernel(const float* __restrict__ src, float* __restrict__ dst)
{
    __shared__ float tile[32][33];
    int x = blockIdx.x * 32 + threadIdx.x;
    int y0 = blockIdx.y * 32 + threadIdx.y;
#pragma unroll
    for (int j = 0; j < 32; j += 8)
        tile[threadIdx.y + j][threadIdx.x] = src[(size_t)(y0 + j) * DD + x];
    __syncthreads();
    x = blockIdx.y * 32 + threadIdx.x;
    y0 = blockIdx.x * 32 + threadIdx.y;
#pragma unroll
    for (int j = 0; j < 32; j += 8)
        dst[(size_t)(y0 + j) * DD + x] = tile[threadIdx.x][threadIdx.y + j];
}

// ----------------------------------------------------------------------------
// rowdot: out[r] = dot(A[r, 0:1024], v) + (addp ? addp[0] : 0)
// ----------------------------------------------------------------------------
__global__ void rowdot_kernel(const float* __restrict__ A, const float* __restrict__ v,
                              float* __restrict__ out, const float* __restrict__ addp,
                              int rows)
{
    int gw = (blockIdx.x * 256 + threadIdx.x) >> 5;
    int lane = threadIdx.x & 31;
    if (gw >= rows) return;
    const float* row = A + (size_t)gw * DD;
    float s = 0.f;
#pragma unroll
    for (int d = lane * 4; d < DD; d += 128) {
        float4 x = *reinterpret_cast<const float4*>(row + d);
        float4 y = *reinterpret_cast<const float4*>(v + d);
        s += x.x * y.x + x.y * y.y + x.z * y.z + x.w * y.w;
    }
#pragma unroll
    for (int off = 16; off > 0; off >>= 1) s += __shfl_down_sync(0xffffffffu, s, off);
    if (lane == 0) out[gw] = s + (addp ? addp[0] : 0.f);
}

// ----------------------------------------------------------------------------
// slots init
// ----------------------------------------------------------------------------
__global__ void init_slots_kernel(const float* __restrict__ mu, float* __restrict__ slots)
{
    int idx = blockIdx.x * 256 + threadIdx.x;
    slots[idx] = mu[idx & 16383];
}

// ----------------------------------------------------------------------------
// LayerNorm
// ----------------------------------------------------------------------------
__global__ void ln_rows_kernel(const float* __restrict__ x, const float* __restrict__ g,
                               const float* __restrict__ b, float* __restrict__ y)
{
    int row = blockIdx.x;
    int t = threadIdx.x;
    const float4* xr = reinterpret_cast<const float4*>(x + (size_t)row * DD);
    float4 v = xr[t];
    float s1 = v.x + v.y + v.z + v.w;
    float s2 = v.x * v.x + v.y * v.y + v.z * v.z + v.w * v.w;
    int lane = t & 31, w = t >> 5;
#pragma unroll
    for (int off = 16; off > 0; off >>= 1) {
        s1 += __shfl_down_sync(0xffffffffu, s1, off);
        s2 += __shfl_down_sync(0xffffffffu, s2, off);
    }
    __shared__ float ss1[8], ss2[8];
    __shared__ float smu, srstd;
    if (lane == 0) { ss1[w] = s1; ss2[w] = s2; }
    __syncthreads();
    if (t == 0) {
        float S = 0.f, Q = 0.f;
#pragma unroll
        for (int i = 0; i < 8; i++) { S += ss1[i]; Q += ss2[i]; }
        float mu = S * (1.f / DD);
        float var = Q * (1.f / DD) - mu * mu;
        smu = mu; srstd = rsqrtf(var + EPS_LN);
    }
    __syncthreads();
    float mu = smu, rr = srstd;
    float4 gv = reinterpret_cast<const float4*>(g)[t];
    float4 bv = reinterpret_cast<const float4*>(b)[t];
    float4 o;
    o.x = (v.x - mu) * rr * gv.x + bv.x;
    o.y = (v.y - mu) * rr * gv.y + bv.y;
    o.z = (v.z - mu) * rr * gv.z + bv.z;
    o.w = (v.w - mu) * rr * gv.w + bv.w;
    reinterpret_cast<float4*>(y + (size_t)row * DD)[t] = o;
}

// ----------------------------------------------------------------------------
// softmax over k + partial row sums
// ----------------------------------------------------------------------------
__global__ void softmax_kernel(float* __restrict__ attn, float* __restrict__ partial)
{
    int blk = blockIdx.x;
    int b = blk >> 4;
    int s = (blk & 15) * 256 + threadIdx.x;
    float* a = attn + ((size_t)b * SS + s) * KK;
    float v[16];
    float4* a4 = reinterpret_cast<float4*>(a);
#pragma unroll
    for (int i = 0; i < 4; i++) {
        float4 x = a4[i];
        v[i * 4 + 0] = x.x; v[i * 4 + 1] = x.y; v[i * 4 + 2] = x.z; v[i * 4 + 3] = x.w;
    }
    float mx = v[0];
#pragma unroll
    for (int k = 1; k < 16; k++) mx = fmaxf(mx, v[k]);
    float sum = 0.f;
#pragma unroll
    for (int k = 0; k < 16; k++) { v[k] = expf(v[k] - mx); sum += v[k]; }
    float inv = 1.f / sum;
#pragma unroll
    for (int k = 0; k < 16; k++) v[k] *= inv;
#pragma unroll
    for (int i = 0; i < 4; i++) {
        float4 x;
        x.x = v[i * 4 + 0]; x.y = v[i * 4 + 1]; x.z = v[i * 4 + 2]; x.w = v[i * 4 + 3];
        a4[i] = x;
    }
    int lane = threadIdx.x & 31, w = threadIdx.x >> 5;
    __shared__ float ws[8][16];
#pragma unroll
    for (int k = 0; k < 16; k++) {
        float x = v[k];
#pragma unroll
        for (int off = 16; off > 0; off >>= 1) x += __shfl_down_sync(0xffffffffu, x, off);
        if (lane == 0) ws[w][k] = x;
    }
    __syncthreads();
    if (threadIdx.x < 16) {
        float sacc = 0.f;
#pragma unroll
        for (int ww = 0; ww < 8; ww++) sacc += ws[ww][threadIdx.x];
        partial[(size_t)blk * KK + threadIdx.x] = sacc;
    }
}

__global__ void rowsum_kernel(const float* __restrict__ partial, float* __restrict__ rowsum,
                              float* __restrict__ rowf)
{
    int t = threadIdx.x;
    int b = t >> 4, k = t & 15;
    float s = 0.f;
#pragma unroll
    for (int c = 0; c < 16; c++) s += partial[((size_t)(b * 16 + c)) * KK + k];
    rowsum[t] = s;
    rowf[t] = s / (s + EPS_ATTN);
}

// ----------------------------------------------------------------------------
// GRU combine
// ----------------------------------------------------------------------------
__global__ void gru_kernel(const float* __restrict__ gi, const float* __restrict__ gh,
                           float* __restrict__ slots)
{
    int idx = blockIdx.x * 256 + threadIdx.x;
    int m = idx >> 10, d = idx & 1023;
    size_t base = (size_t)m * 3072 + d;
    float ir = gi[base], iz = gi[base + 1024], in_ = gi[base + 2048];
    float hr = gh[base], hz = gh[base + 1024], hn  = gh[base + 2048];
    float r = 1.f / (1.f + expf(-(ir + hr)));
    float z = 1.f / (1.f + expf(-(iz + hz)));
    float n = tanhf(in_ + r * hn);
    float sp = slots[idx];
    slots[idx] = (1.f - z) * n + z * sp;
}

// ----------------------------------------------------------------------------
// output writers
// ----------------------------------------------------------------------------
__global__ void copy_kernel(const float* __restrict__ src, float* __restrict__ dst)
{
    int idx = blockIdx.x * 256 + threadIdx.x;
    dst[idx] = src[idx];
}

__global__ void attn_out_kernel(const float* __restrict__ attn, float* __restrict__ out)
{
    int idx = blockIdx.x * 256 + threadIdx.x;
    int s = idx & 4095;
    int k = (idx >> 12) & 15;
    int b = idx >> 16;
    out[idx] = attn[((size_t)b * SS + s) * KK + k];
}

// ----------------------------------------------------------------------------
// host
// ----------------------------------------------------------------------------
extern "C" void kernel_launch(void* const* d_in, const int* in_sizes, int n_in,
                              void* d_out, int out_size)
{
    const float* tokens  = (const float*)d_in[0];
    const float* slot_mu = (const float*)d_in[1];
    const float* Wq   = (const float*)d_in[2];
    const float* bq   = (const float*)d_in[3];
    const float* Wk   = (const float*)d_in[4];
    const float* bk   = (const float*)d_in[5];
    const float* Wv   = (const float*)d_in[6];
    const float* bv   = (const float*)d_in[7];
    const float* W_ih = (const float*)d_in[8];
    const float* b_ih = (const float*)d_in[9];
    const float* W_hh = (const float*)d_in[10];
    const float* b_hh = (const float*)d_in[11];
    const float* W1   = (const float*)d_in[12];
    const float* b1   = (const float*)d_in[13];
    const float* W2   = (const float*)d_in[14];
    const float* b2   = (const float*)d_in[15];
    const float* gam_slots = (const float*)d_in[16];
    const float* bet_slots = (const float*)d_in[17];
    const float* gam_mlp   = (const float*)d_in[18];
    const float* bet_mlp   = (const float*)d_in[19];
    float* out = (float*)d_out;

    float *attn, *partial, *rowsum, *rowf, *qd, *slots, *lnbuf, *qkbuf,
          *updbuf, *upd2, *gibuf, *ghbuf, *h1buf, *wkT, *wqT, *Pt, *wqbk,
          *cvec, *bqbk, *zero;
    cudaGetSymbolAddress((void**)&attn,   g_attn);
    cudaGetSymbolAddress((void**)&partial,g_partial);
    cudaGetSymbolAddress((void**)&rowsum, g_rowsum);
    cudaGetSymbolAddress((void**)&rowf,   g_rowf);
    cudaGetSymbolAddress((void**)&qd,     g_qd);
    cudaGetSymbolAddress((void**)&slots,  g_slots);
    cudaGetSymbolAddress((void**)&lnbuf,  g_lnbuf);
    cudaGetSymbolAddress((void**)&qkbuf,  g_qkbuf);
    cudaGetSymbolAddress((void**)&updbuf, g_updbuf);
    cudaGetSymbolAddress((void**)&upd2,   g_upd2);
    cudaGetSymbolAddress((void**)&gibuf,  g_gibuf);
    cudaGetSymbolAddress((void**)&ghbuf,  g_ghbuf);
    cudaGetSymbolAddress((void**)&h1buf,  g_h1buf);
    cudaGetSymbolAddress((void**)&wkT,    g_wkT);
    cudaGetSymbolAddress((void**)&wqT,    g_wqT);
    cudaGetSymbolAddress((void**)&Pt,     g_Pt);
    cudaGetSymbolAddress((void**)&wqbk,   g_wqbk);
    cudaGetSymbolAddress((void**)&cvec,   g_cvec);
    cudaGetSymbolAddress((void**)&bqbk,   g_bqbk);
    cudaGetSymbolAddress((void**)&zero,   g_zero);

    cudaFuncSetAttribute(logits_tc, cudaFuncAttributeMaxDynamicSharedMemorySize, LTC_SMEM);

    // ---- one-time prep ----
    transpose_kernel<<<dim3(32, 32), dim3(32, 8)>>>(Wk, wkT);
    transpose_kernel<<<dim3(32, 32), dim3(32, 8)>>>(Wq, wqT);
    // Pt[e,f] = sum_d Wk[d,e] Wq[d,f]  (NT gemm: A=wkT, W=wqT)
    gemm_tf32<64, 64, 32, 16, 0, false, 3, false>
        <<<dim3(DD / 64, DD / 64), 256>>>(wkT, wqT, zero, nullptr, Pt, DD, DD);
    rowdot_kernel<<<128, 256>>>(wqT, bk, wqbk, nullptr, DD);   // wqbk[f] = Wq[:,f].bk
    rowdot_kernel<<<128, 256>>>(wkT, bq, cvec, nullptr, DD);   // cvec[e] = bq.Wk[:,e]
    rowdot_kernel<<<1, 256>>>(bq, bk, bqbk, nullptr, 1);       // bq.bk
    init_slots_kernel<<<SLOT_ELEMS / 256, 256>>>(slot_mu, slots);

    for (int it = 0; it < ITERS; it++) {
        // ln = LN(slots); q' = ln @ Pt^T(NT) + cvec; qd = ln.wqbk + bqbk
        ln_rows_kernel<<<BB * KK, 256>>>(slots, gam_slots, bet_slots, lnbuf);
        gemm_tf32<64, 64, 32, 16, 0, false, 3, false>
            <<<dim3(DD / 64, BB * KK / 64), 256>>>(lnbuf, Pt, cvec, nullptr, qkbuf, DD, DD);
        rowdot_kernel<<<32, 256>>>(lnbuf, wqbk, qd, bqbk, BB * KK);

        // logits (tensor) -> softmax over slots -> row sums
        logits_tc<<<dim3(SS / 256, BB), 256, LTC_SMEM>>>(qkbuf, tokens, qd, attn);
        softmax_kernel<<<BB * 16, 256>>>(attn, partial);
        rowsum_kernel<<<1, 256>>>(partial, rowsum, rowf);

        // U = attn_n @ tokens (tensor), then updates = U @ Wv^T + f*bv
        updates_tc<<<dim3(DD / 128, BB), 256>>>(attn, rowsum, tokens, updbuf);
        gemm_tf32<64, 64, 32, 16, 0, false, 3, true>
            <<<dim3(DD / 64, BB * KK / 64), 256>>>(updbuf, Wv, bv, rowf, upd2, DD, DD);

        // GRU
        gemm_tf32<64, 64, 32, 16, 0, false, 1, false>
            <<<dim3(3 * DD / 64, BB * KK / 64), 256>>>(upd2, W_ih, b_ih, nullptr, gibuf, 3 * DD, DD);
        gemm_tf32<64, 64, 32, 16, 0, false, 1, false>
            <<<dim3(3 * DD / 64, BB * KK / 64), 256>>>(slots, W_hh, b_hh, nullptr, ghbuf, 3 * DD, DD);
        gru_kernel<<<SLOT_ELEMS / 256, 256>>>(gibuf, ghbuf, slots);

        // MLP residual
        ln_rows_kernel<<<BB * KK, 256>>>(slots, gam_mlp, bet_mlp, lnbuf);
        gemm_tf32<64, 64, 32, 16, 1, false, 1, false>
            <<<dim3(4 * DD / 64, BB * KK / 64), 256>>>(lnbuf, W1, b1, nullptr, h1buf, 4 * DD, DD);
        gemm_tf32<64, 64, 32, 16, 0, true, 1, false>
            <<<dim3(DD / 64, BB * KK / 64), 256>>>(h1buf, W2, b2, nullptr, slots, DD, 4 * DD);
    }

    copy_kernel<<<SLOT_ELEMS / 256, 256>>>(slots, out);
    attn_out_kernel<<<(BB * KK * SS) / 256, 256>>>(attn, out + SLOT_ELEMS);
}